// round 1
// baseline (speedup 1.0000x reference)
#include <cuda_runtime.h>
#include <cuda_fp16.h>
#include <cstdint>

#define Bb 16
#define Tt 16384
#define Cc 64
#define Ll 10
#define NT 128

// ---------------- scratch (static __device__, no allocs) ----------------
__device__ float  g_h[2][Bb * Cc * Tt];      // fp32 residual stream, double buffered
__device__ float  g_skip[Bb * Cc * Tt];      // fp32 skip accumulator
__device__ __half g_W1[Ll * 128 * 192];      // interleaved (filt/gate) dilated-conv weights
__device__ __half g_W2[Ll * 128 * 64];       // interleaved (res/skip) 1x1 weights
__device__ float  g_b1[Ll * 128];
__device__ float  g_b2[Ll * 128];

// ---------------- mma helper ----------------
__device__ __forceinline__ void mma16816(float c[4], const uint32_t a[4], const uint32_t b[2]) {
    asm volatile(
        "mma.sync.aligned.m16n8k16.row.col.f32.f16.f16.f32 "
        "{%0,%1,%2,%3}, {%4,%5,%6,%7}, {%8,%9}, {%0,%1,%2,%3};\n"
        : "+f"(c[0]), "+f"(c[1]), "+f"(c[2]), "+f"(c[3])
        : "r"(a[0]), "r"(a[1]), "r"(a[2]), "r"(a[3]), "r"(b[0]), "r"(b[1]));
}

// ---------------- weight prep: build interleaved fp16 matrices ----------------
// W1 row layout: m16-tile 'tile' rows 0..7 = filt out-ch (tile*8+rr), rows 8..15 = gate.
// W1 col layout: r = k*64 + i  (tap k pairs with input h[t - (2-k)*d]).
__global__ void prep_kernel(const float* __restrict__ fw, const float* __restrict__ fb,
                            const float* __restrict__ gw, const float* __restrict__ gb,
                            const float* __restrict__ rw, const float* __restrict__ rb,
                            const float* __restrict__ sw, const float* __restrict__ sb) {
    int idx = blockIdx.x * blockDim.x + threadIdx.x;
    if (idx < Ll * 128 * 192) {
        int l = idx / (128 * 192);
        int rem = idx - l * 128 * 192;
        int row = rem / 192, r = rem - row * 192;
        int k = r >> 6, i = r & 63;
        int tile = row >> 4, rr = row & 15;
        int o = tile * 8 + (rr & 7);
        int src = ((l * 64 + o) * 64 + i) * 3 + k;
        float v = (rr < 8) ? fw[src] : gw[src];
        g_W1[idx] = __float2half_rn(v);
    }
    if (idx < Ll * 128 * 64) {
        int l = idx / (128 * 64);
        int rem = idx - l * 128 * 64;
        int row = rem >> 6, i = rem & 63;
        int tile = row >> 4, rr = row & 15;
        int o = tile * 8 + (rr & 7);
        int src = (l * 64 + o) * 64 + i;
        float v = (rr < 8) ? rw[src] : sw[src];
        g_W2[idx] = __float2half_rn(v);
    }
    if (idx < Ll * 128) {
        int l = idx >> 7, row = idx & 127;
        int tile = row >> 4, rr = row & 15;
        int o = tile * 8 + (rr & 7);
        g_b1[idx] = (rr < 8) ? fb[l * 64 + o] : gb[l * 64 + o];
        g_b2[idx] = (rr < 8) ? rb[l * 64 + o] : sb[l * 64 + o];
    }
}

// ---------------- input 1x1 conv: x[B,T,F=32] -> h0[B,C=64,T] (fp32) ----------------
__global__ __launch_bounds__(256) void input_conv_kernel(const float* __restrict__ x,
                                                         const float* __restrict__ w,
                                                         const float* __restrict__ bias) {
    __shared__ float sx[128 * 33];
    __shared__ float swt[64 * 32];
    __shared__ float sb[64];
    int tid = threadIdx.x;
    int n0 = blockIdx.x * 128;
    int b = n0 >> 14, t0 = n0 & 16383;

    for (int idx = tid; idx < 128 * 32; idx += 256) {
        int j = idx >> 5, f = idx & 31;
        sx[j * 33 + f] = x[(b * Tt + t0 + j) * 32 + f];
    }
    for (int idx = tid; idx < 2048; idx += 256) swt[idx] = w[idx];
    if (tid < 64) sb[tid] = bias[tid];
    __syncthreads();

    for (int oi = tid; oi < 64 * 128; oi += 256) {
        int c = oi >> 7, j = oi & 127;
        float s = sb[c];
#pragma unroll
        for (int f = 0; f < 32; f++) s = fmaf(swt[c * 32 + f], sx[j * 33 + f], s);
        g_h[0][(b * 64 + c) * Tt + t0 + j] = s;
    }
}

// ---------------- per-layer fused kernel ----------------
// smem layout (bytes): [0,51200) sW1 (aliased: [0,18432) sW2, [18432,35328) sAct)
//                      [51200,100864) sX  (n-major [128][194] halves)
#define ST_W1 200
#define ST_W2 72
#define ST_ACT 66
#define ST_X 194
#define SMEM_BYTES 100864

__global__ __launch_bounds__(256, 2) void layer_kernel(int l, int d, int bufin, int first) {
    extern __shared__ char smem[];
    __half* sW1  = reinterpret_cast<__half*>(smem);
    __half* sW2  = reinterpret_cast<__half*>(smem);
    __half* sAct = reinterpret_cast<__half*>(smem + 18432);
    __half* sX   = reinterpret_cast<__half*>(smem + 51200);

    const int tid = threadIdx.x;
    const int lane = tid & 31, wid = tid >> 5;
    const int g = lane >> 2, tig = lane & 3;
    const int wm = (wid >> 1) * 32;   // row base (2 m16 tiles)
    const int wn = (wid & 1) * 64;    // col base (8 n8 tiles)

    const int n0 = blockIdx.x * NT;
    const int b = n0 >> 14;
    const int t0 = n0 & 16383;

    const float* __restrict__ hin = g_h[bufin];
    float* __restrict__ hout = g_h[bufin ^ 1];

    // load W1 (interleaved) to smem
    const __half* __restrict__ W1 = g_W1 + l * (128 * 192);
    for (int idx = tid; idx < 128 * 192; idx += 256) {
        int r = idx / 192, c = idx - r * 192;
        sW1[r * ST_W1 + c] = W1[idx];
    }
    // gather 3 dilated taps, fp32 -> fp16, n-major
    for (int idx = tid; idx < 192 * NT; idx += 256) {
        int j = idx & (NT - 1);
        int r = idx >> 7;                 // 0..191: r = k*64 + i
        int k = r >> 6, i = r & 63;
        int t = t0 + j - (2 - k) * d;
        float v = (t >= 0) ? hin[(b * 64 + i) * Tt + t] : 0.f;
        sX[j * ST_X + r] = __float2half_rn(v);
    }
    __syncthreads();

    // ---- GEMM1: [128 x 192] x [192 x 128] ----
    float acc[2][8][4];
#pragma unroll
    for (int mt = 0; mt < 2; mt++)
#pragma unroll
        for (int nt = 0; nt < 8; nt++)
#pragma unroll
            for (int q = 0; q < 4; q++) acc[mt][nt][q] = 0.f;

#pragma unroll 4
    for (int kb = 0; kb < 192; kb += 16) {
        uint32_t bf[8][2];
#pragma unroll
        for (int nt = 0; nt < 8; nt++) {
            const __half* p = &sX[(wn + nt * 8 + g) * ST_X + kb + 2 * tig];
            bf[nt][0] = *reinterpret_cast<const uint32_t*>(p);
            bf[nt][1] = *reinterpret_cast<const uint32_t*>(p + 8);
        }
#pragma unroll
        for (int mt = 0; mt < 2; mt++) {
            const __half* pa = &sW1[(wm + mt * 16 + g) * ST_W1 + kb + 2 * tig];
            uint32_t a[4];
            a[0] = *reinterpret_cast<const uint32_t*>(pa);
            a[1] = *reinterpret_cast<const uint32_t*>(pa + 8 * ST_W1);
            a[2] = *reinterpret_cast<const uint32_t*>(pa + 8);
            a[3] = *reinterpret_cast<const uint32_t*>(pa + 8 * ST_W1 + 8);
#pragma unroll
            for (int nt = 0; nt < 8; nt++) mma16816(acc[mt][nt], a, bf[nt]);
        }
    }
    __syncthreads();   // everyone done reading sW1 region

    // load W2 into aliased region
    const __half* __restrict__ W2 = g_W2 + l * (128 * 64);
    for (int idx = tid; idx < 128 * 64; idx += 256) {
        int r = idx >> 6, c = idx & 63;
        sW2[r * ST_W2 + c] = W2[idx];
    }
    // epilogue1: act = tanh(filt) * sigmoid(gate) -> sAct (fp16, n-major)
#pragma unroll
    for (int mt = 0; mt < 2; mt++) {
        int row = wm + mt * 16 + g;       // g < 8, so this is the "filt" row
        int tile = row >> 4, rr = row & 7;
        int o = tile * 8 + rr;
        float bfil = g_b1[l * 128 + tile * 16 + rr];
        float bgat = g_b1[l * 128 + tile * 16 + 8 + rr];
#pragma unroll
        for (int nt = 0; nt < 8; nt++) {
            int j0 = wn + nt * 8 + 2 * tig;
            float f0 = 1.f - 2.f / (__expf(2.f * (acc[mt][nt][0] + bfil)) + 1.f);
            float f1 = 1.f - 2.f / (__expf(2.f * (acc[mt][nt][1] + bfil)) + 1.f);
            float s0 = 1.f / (1.f + __expf(-(acc[mt][nt][2] + bgat)));
            float s1 = 1.f / (1.f + __expf(-(acc[mt][nt][3] + bgat)));
            sAct[j0 * ST_ACT + o] = __float2half_rn(f0 * s0);
            sAct[(j0 + 1) * ST_ACT + o] = __float2half_rn(f1 * s1);
        }
    }
    __syncthreads();

    // ---- GEMM2: [128 x 64] x [64 x 128] ----
    float acc2[2][8][4];
#pragma unroll
    for (int mt = 0; mt < 2; mt++)
#pragma unroll
        for (int nt = 0; nt < 8; nt++)
#pragma unroll
            for (int q = 0; q < 4; q++) acc2[mt][nt][q] = 0.f;

#pragma unroll
    for (int kb = 0; kb < 64; kb += 16) {
        uint32_t bf[8][2];
#pragma unroll
        for (int nt = 0; nt < 8; nt++) {
            const __half* p = &sAct[(wn + nt * 8 + g) * ST_ACT + kb + 2 * tig];
            bf[nt][0] = *reinterpret_cast<const uint32_t*>(p);
            bf[nt][1] = *reinterpret_cast<const uint32_t*>(p + 8);
        }
#pragma unroll
        for (int mt = 0; mt < 2; mt++) {
            const __half* pa = &sW2[(wm + mt * 16 + g) * ST_W2 + kb + 2 * tig];
            uint32_t a[4];
            a[0] = *reinterpret_cast<const uint32_t*>(pa);
            a[1] = *reinterpret_cast<const uint32_t*>(pa + 8 * ST_W2);
            a[2] = *reinterpret_cast<const uint32_t*>(pa + 8);
            a[3] = *reinterpret_cast<const uint32_t*>(pa + 8 * ST_W2 + 8);
#pragma unroll
            for (int nt = 0; nt < 8; nt++) mma16816(acc2[mt][nt], a, bf[nt]);
        }
    }

    // epilogue2: h' = (h + residual)*0.7071 ; skip_sum += skip
#pragma unroll
    for (int mt = 0; mt < 2; mt++) {
        int row = wm + mt * 16 + g;
        int tile = row >> 4, rr = row & 7;
        int o = tile * 8 + rr;
        float brs = g_b2[l * 128 + tile * 16 + rr];
        float bsk = g_b2[l * 128 + tile * 16 + 8 + rr];
        int base = (b * 64 + o) * Tt + t0;
#pragma unroll
        for (int nt = 0; nt < 8; nt++) {
            int j0 = wn + nt * 8 + 2 * tig;
            float2 hc = *reinterpret_cast<const float2*>(&hin[base + j0]);
            float2 ho;
            ho.x = (hc.x + acc2[mt][nt][0] + brs) * 0.7071f;
            ho.y = (hc.y + acc2[mt][nt][1] + brs) * 0.7071f;
            *reinterpret_cast<float2*>(&hout[base + j0]) = ho;

            float2* sp = reinterpret_cast<float2*>(&g_skip[base + j0]);
            float2 sv;
            sv.x = acc2[mt][nt][2] + bsk;
            sv.y = acc2[mt][nt][3] + bsk;
            if (!first) {
                float2 old = *sp;
                sv.x += old.x; sv.y += old.y;
            }
            *sp = sv;
        }
    }
}

// ---------------- output head: relu -> 1x1 (64->64) -> relu -> 1x1 (64->1) ----------------
__global__ __launch_bounds__(256) void output_kernel(const float* __restrict__ ow1,
                                                     const float* __restrict__ ob1,
                                                     const float* __restrict__ ow2,
                                                     const float* __restrict__ ob2,
                                                     float* __restrict__ out) {
    __shared__ float sS[64 * 65];    // skip tile, [c][t]
    __shared__ float sW[64 * 68];    // ow1 transposed: [c][u]
    __shared__ float sw2[64], sb1[64];
    int tid = threadIdx.x;
    int n0 = blockIdx.x * 64;
    int b = n0 >> 14, t0 = n0 & 16383;

    for (int idx = tid; idx < 64 * 64; idx += 256) {
        int c = idx >> 6, tt = idx & 63;
        sS[c * 65 + tt] = g_skip[(b * 64 + c) * Tt + t0 + tt];
    }
    for (int idx = tid; idx < 64 * 64; idx += 256) {
        int u = idx >> 6, c = idx & 63;
        sW[c * 68 + u] = ow1[idx];             // ow1[u][c]
    }
    if (tid < 64) { sw2[tid] = ow2[tid]; sb1[tid] = ob1[tid]; }
    __syncthreads();

    int tl = tid >> 2, p = tid & 3;            // 64 timesteps x 4-thread quads
    float acc[16];
#pragma unroll
    for (int q = 0; q < 16; q++) acc[q] = sb1[4 * q + p];
#pragma unroll 4
    for (int c = 0; c < 64; c++) {
        float v = fmaxf(sS[c * 65 + tl], 0.f);
#pragma unroll
        for (int q = 0; q < 16; q++) acc[q] = fmaf(sW[c * 68 + 4 * q + p], v, acc[q]);
    }
    float y = 0.f;
#pragma unroll
    for (int q = 0; q < 16; q++) y += sw2[4 * q + p] * fmaxf(acc[q], 0.f);
    y += __shfl_xor_sync(0xFFFFFFFFu, y, 1);
    y += __shfl_xor_sync(0xFFFFFFFFu, y, 2);
    if (p == 0) out[b * Tt + t0 + tl] = y + ob2[0];
}

// ---------------- launcher ----------------
extern "C" void kernel_launch(void* const* d_in, const int* in_sizes, int n_in,
                              void* d_out, int out_size) {
    (void)in_sizes; (void)n_in; (void)out_size;
    const float* x    = (const float*)d_in[0];
    const float* w_in = (const float*)d_in[1];
    const float* b_in = (const float*)d_in[2];
    const float* fw   = (const float*)d_in[3];
    const float* fb   = (const float*)d_in[4];
    const float* gw   = (const float*)d_in[5];
    const float* gb   = (const float*)d_in[6];
    const float* rw   = (const float*)d_in[7];
    const float* rb   = (const float*)d_in[8];
    const float* sw   = (const float*)d_in[9];
    const float* sb   = (const float*)d_in[10];
    const float* ow1  = (const float*)d_in[11];
    const float* ob1  = (const float*)d_in[12];
    const float* ow2  = (const float*)d_in[13];
    const float* ob2  = (const float*)d_in[14];
    float* out = (float*)d_out;

    static const int dil[Ll] = {1, 2, 4, 8, 16, 32, 64, 128, 256, 512};

    cudaFuncSetAttribute((const void*)layer_kernel,
                         cudaFuncAttributeMaxDynamicSharedMemorySize, SMEM_BYTES);

    prep_kernel<<<960, 256>>>(fw, fb, gw, gb, rw, rb, sw, sb);
    input_conv_kernel<<<(Bb * Tt) / 128, 256>>>(x, w_in, b_in);

    int buf = 0;
    for (int l = 0; l < Ll; l++) {
        layer_kernel<<<(Bb * Tt) / NT, 256, SMEM_BYTES>>>(l, dil[l], buf, l == 0);
        buf ^= 1;
    }
    output_kernel<<<(Bb * Tt) / 64, 256>>>(ow1, ob1, ow2, ob2, out);
}

// round 3
// speedup vs baseline: 1.0159x; 1.0159x over previous
#include <cuda_runtime.h>
#include <cuda_fp16.h>
#include <cstdint>

#define Bb 16
#define Tt 16384
#define Cc 64
#define Ll 10
#define NT 128

// ---------------- scratch (static __device__, no allocs) ----------------
__device__ float  g_h[2][Bb * Cc * Tt];      // fp32 residual stream, double buffered
__device__ __half g_hh[2][Bb * Cc * Tt];     // fp16 shadow of h (GEMM operand), double buffered
__device__ float  g_skip[Bb * Cc * Tt];      // fp32 skip accumulator
__device__ __half g_W1[Ll * 128 * 192];      // interleaved (filt/gate) dilated-conv weights
__device__ __half g_W2[Ll * 128 * 64];       // interleaved (res/skip) 1x1 weights
__device__ float  g_b1[Ll * 128];
__device__ float  g_b2[Ll * 128];

// ---------------- mma / ldmatrix helpers ----------------
__device__ __forceinline__ void mma16816(float c[4], const uint32_t a[4], const uint32_t b[2]) {
    asm volatile(
        "mma.sync.aligned.m16n8k16.row.col.f32.f16.f16.f32 "
        "{%0,%1,%2,%3}, {%4,%5,%6,%7}, {%8,%9}, {%0,%1,%2,%3};\n"
        : "+f"(c[0]), "+f"(c[1]), "+f"(c[2]), "+f"(c[3])
        : "r"(a[0]), "r"(a[1]), "r"(a[2]), "r"(a[3]), "r"(b[0]), "r"(b[1]));
}
__device__ __forceinline__ void ldsm4(uint32_t r[4], uint32_t addr) {
    asm volatile("ldmatrix.sync.aligned.m8n8.x4.shared.b16 {%0,%1,%2,%3}, [%4];"
                 : "=r"(r[0]), "=r"(r[1]), "=r"(r[2]), "=r"(r[3]) : "r"(addr));
}
__device__ __forceinline__ void ldsm4t(uint32_t r[4], uint32_t addr) {
    asm volatile("ldmatrix.sync.aligned.m8n8.x4.trans.shared.b16 {%0,%1,%2,%3}, [%4];"
                 : "=r"(r[0]), "=r"(r[1]), "=r"(r[2]), "=r"(r[3]) : "r"(addr));
}

// ---------------- weight prep: build interleaved fp16 matrices ----------------
__global__ void prep_kernel(const float* __restrict__ fw, const float* __restrict__ fb,
                            const float* __restrict__ gw, const float* __restrict__ gb,
                            const float* __restrict__ rw, const float* __restrict__ rb,
                            const float* __restrict__ sw, const float* __restrict__ sb) {
    int idx = blockIdx.x * blockDim.x + threadIdx.x;
    if (idx < Ll * 128 * 192) {
        int l = idx / (128 * 192);
        int rem = idx - l * 128 * 192;
        int row = rem / 192, r = rem - row * 192;
        int k = r >> 6, i = r & 63;
        int tile = row >> 4, rr = row & 15;
        int o = tile * 8 + (rr & 7);
        int src = ((l * 64 + o) * 64 + i) * 3 + k;
        float v = (rr < 8) ? fw[src] : gw[src];
        g_W1[idx] = __float2half_rn(v);
    }
    if (idx < Ll * 128 * 64) {
        int l = idx / (128 * 64);
        int rem = idx - l * 128 * 64;
        int row = rem >> 6, i = rem & 63;
        int tile = row >> 4, rr = row & 15;
        int o = tile * 8 + (rr & 7);
        int src = (l * 64 + o) * 64 + i;
        float v = (rr < 8) ? rw[src] : sw[src];
        g_W2[idx] = __float2half_rn(v);
    }
    if (idx < Ll * 128) {
        int l = idx >> 7, row = idx & 127;
        int tile = row >> 4, rr = row & 15;
        int o = tile * 8 + (rr & 7);
        g_b1[idx] = (rr < 8) ? fb[l * 64 + o] : gb[l * 64 + o];
        g_b2[idx] = (rr < 8) ? rb[l * 64 + o] : sb[l * 64 + o];
    }
}

// ---------------- input 1x1 conv: x[B,T,F=32] -> h0[B,C=64,T] ----------------
__global__ __launch_bounds__(256) void input_conv_kernel(const float* __restrict__ x,
                                                         const float* __restrict__ w,
                                                         const float* __restrict__ bias) {
    __shared__ float sx[128 * 33];
    __shared__ float swt[64 * 32];
    __shared__ float sb[64];
    int tid = threadIdx.x;
    int n0 = blockIdx.x * 128;
    int b = n0 >> 14, t0 = n0 & 16383;

    for (int idx = tid; idx < 128 * 32; idx += 256) {
        int j = idx >> 5, f = idx & 31;
        sx[j * 33 + f] = x[(b * Tt + t0 + j) * 32 + f];
    }
    for (int idx = tid; idx < 2048; idx += 256) swt[idx] = w[idx];
    if (tid < 64) sb[tid] = bias[tid];
    __syncthreads();

    for (int oi = tid; oi < 64 * 128; oi += 256) {
        int c = oi >> 7, j = oi & 127;
        float s = sb[c];
#pragma unroll
        for (int f = 0; f < 32; f++) s = fmaf(swt[c * 32 + f], sx[j * 33 + f], s);
        int ofs = (b * 64 + c) * Tt + t0 + j;
        g_h[0][ofs] = s;
        g_hh[0][ofs] = __float2half_rn(s);
    }
}

// ---------------- per-layer fused kernel ----------------
// smem (bytes): [0,51200) sW1  (aliased after GEMM1: [0,18432) sW2, [18432,35840) sAct)
//               [51200,103424) sX  (k-major [192 rows][136 halves])
#define ST_X   136
#define ST_W1  200
#define ST_W2  72
#define ST_ACT 136
#define OFF_W2  0
#define OFF_ACT 18432
#define OFF_X   51200
#define SMEM_BYTES 103424

__global__ __launch_bounds__(256, 2) void layer_kernel(int l, int d, int bufin, int first) {
    extern __shared__ char smem[];
    __half* sW1  = reinterpret_cast<__half*>(smem);
    __half* sW2  = reinterpret_cast<__half*>(smem + OFF_W2);
    __half* sAct = reinterpret_cast<__half*>(smem + OFF_ACT);
    __half* sX   = reinterpret_cast<__half*>(smem + OFF_X);
    const uint32_t smem_u32 = (uint32_t)__cvta_generic_to_shared(smem);

    const int tid = threadIdx.x;
    const int lane = tid & 31, wid = tid >> 5;
    const int g = lane >> 2, tig = lane & 3;
    const int wm = (wid >> 1) * 32;   // row base (2 m16 tiles)
    const int wn = (wid & 1) * 64;    // col base (8 n8 tiles)
    const int l15 = lane & 15;
    const int lc8 = (lane >> 4) << 3;

    const int n0 = blockIdx.x * NT;
    const int b = n0 >> 14;
    const int t0 = n0 & 16383;

    const float* __restrict__ hin = g_h[bufin];
    float* __restrict__ hout = g_h[bufin ^ 1];
    const __half* __restrict__ hhin = g_hh[bufin];
    __half* __restrict__ hhout = g_hh[bufin ^ 1];

    // ---- stage W1 (row-major, rows=m interleaved, cols=k) ----
    {
        const uint4* W1v = reinterpret_cast<const uint4*>(g_W1 + l * 128 * 192);
        for (int idx = tid; idx < 3072; idx += 256) {
            int r = idx / 24, c = idx - r * 24;   // 24 uint4 per row
            *reinterpret_cast<uint4*>(sW1 + r * ST_W1 + c * 8) = W1v[idx];
        }
    }
    // ---- gather 3 dilated taps (fp16, k-major: row r = k*64+i, col j) ----
    for (int idx = tid; idx < 192 * 64; idx += 256) {
        int r = idx >> 6, q = idx & 63;
        int j = q * 2;
        int k = r >> 6, i = r & 63;
        int off = (2 - k) * d;
        int t = t0 + j - off;
        const __half* src = hhin + (b * 64 + i) * Tt + t;
        __half2 v;
        if (t >= 0 && !(off & 1)) {
            v = *reinterpret_cast<const __half2*>(src);
        } else {
            __half lo = (t >= 0) ? src[0] : __ushort_as_half(0);
            __half hi = (t + 1 >= 0) ? src[1] : __ushort_as_half(0);
            v = __halves2half2(lo, hi);
        }
        *reinterpret_cast<__half2*>(sX + r * ST_X + j) = v;
    }
    __syncthreads();

    // ---- GEMM1: [128 x 192] x [192 x 128] ----
    float acc[2][8][4];
#pragma unroll
    for (int mt = 0; mt < 2; mt++)
#pragma unroll
        for (int nt = 0; nt < 8; nt++)
#pragma unroll
            for (int q = 0; q < 4; q++) acc[mt][nt][q] = 0.f;

    {
        uint32_t aAddr = smem_u32 + ((wm + l15) * ST_W1 + lc8) * 2;
        uint32_t bAddr = smem_u32 + OFF_X + (l15 * ST_X + wn + lc8) * 2;
#pragma unroll
        for (int kb = 0; kb < 12; kb++) {
            uint32_t a0[4], a1[4];
            ldsm4(a0, aAddr);
            ldsm4(a1, aAddr + 16 * ST_W1 * 2);
            uint32_t bf[4][4];
#pragma unroll
            for (int np = 0; np < 4; np++) ldsm4t(bf[np], bAddr + np * 32);
#pragma unroll
            for (int np = 0; np < 4; np++) {
                mma16816(acc[0][np * 2],     a0, &bf[np][0]);
                mma16816(acc[0][np * 2 + 1], a0, &bf[np][2]);
                mma16816(acc[1][np * 2],     a1, &bf[np][0]);
                mma16816(acc[1][np * 2 + 1], a1, &bf[np][2]);
            }
            aAddr += 32;                // +16 halves in k
            bAddr += 16 * ST_X * 2;     // +16 rows in k
        }
    }
    __syncthreads();   // done reading sW1 region

    // ---- stage W2 into aliased region ----
    {
        const uint4* W2v = reinterpret_cast<const uint4*>(g_W2 + l * 128 * 64);
        for (int idx = tid; idx < 1024; idx += 256) {
            int r = idx >> 3, c = idx & 7;   // 8 uint4 per row
            *reinterpret_cast<uint4*>(sW2 + r * ST_W2 + c * 8) = W2v[idx];
        }
    }
    // ---- epilogue1: act = tanh(filt)*sigmoid(gate) -> sAct (k-major: row=o, col=j) ----
#pragma unroll
    for (int mt = 0; mt < 2; mt++) {
        int tile = (wid >> 1) * 2 + mt;
        int o = tile * 8 + g;
        float bfil = g_b1[l * 128 + tile * 16 + g];
        float bgat = g_b1[l * 128 + tile * 16 + 8 + g];
#pragma unroll
        for (int nt = 0; nt < 8; nt++) {
            int j0 = wn + nt * 8 + 2 * tig;
            float f0 = 1.f - 2.f / (__expf(2.f * (acc[mt][nt][0] + bfil)) + 1.f);
            float f1 = 1.f - 2.f / (__expf(2.f * (acc[mt][nt][1] + bfil)) + 1.f);
            float s0 = 1.f / (1.f + __expf(-(acc[mt][nt][2] + bgat)));
            float s1 = 1.f / (1.f + __expf(-(acc[mt][nt][3] + bgat)));
            *reinterpret_cast<__half2*>(sAct + o * ST_ACT + j0) =
                __floats2half2_rn(f0 * s0, f1 * s1);
        }
    }
    __syncthreads();

    // ---- GEMM2: [128 x 64] x [64 x 128] ----
    float acc2[2][8][4];
#pragma unroll
    for (int mt = 0; mt < 2; mt++)
#pragma unroll
        for (int nt = 0; nt < 8; nt++)
#pragma unroll
            for (int q = 0; q < 4; q++) acc2[mt][nt][q] = 0.f;

    {
        uint32_t aAddr = smem_u32 + OFF_W2 + ((wm + l15) * ST_W2 + lc8) * 2;
        uint32_t bAddr = smem_u32 + OFF_ACT + (l15 * ST_ACT + wn + lc8) * 2;
#pragma unroll
        for (int kb = 0; kb < 4; kb++) {
            uint32_t a0[4], a1[4];
            ldsm4(a0, aAddr);
            ldsm4(a1, aAddr + 16 * ST_W2 * 2);
            uint32_t bf[4][4];
#pragma unroll
            for (int np = 0; np < 4; np++) ldsm4t(bf[np], bAddr + np * 32);
#pragma unroll
            for (int np = 0; np < 4; np++) {
                mma16816(acc2[0][np * 2],     a0, &bf[np][0]);
                mma16816(acc2[0][np * 2 + 1], a0, &bf[np][2]);
                mma16816(acc2[1][np * 2],     a1, &bf[np][0]);
                mma16816(acc2[1][np * 2 + 1], a1, &bf[np][2]);
            }
            aAddr += 32;
            bAddr += 16 * ST_ACT * 2;
        }
    }

    // ---- epilogue2: h' = (h + residual)*0.7071 ; skip_sum += skip ----
#pragma unroll
    for (int mt = 0; mt < 2; mt++) {
        int tile = (wid >> 1) * 2 + mt;
        int o = tile * 8 + g;
        float brs = g_b2[l * 128 + tile * 16 + g];
        float bsk = g_b2[l * 128 + tile * 16 + 8 + g];
        int base = (b * 64 + o) * Tt + t0;
#pragma unroll
        for (int nt = 0; nt < 8; nt++) {
            int j0 = wn + nt * 8 + 2 * tig;
            float2 hc = *reinterpret_cast<const float2*>(&hin[base + j0]);
            float2 ho;
            ho.x = (hc.x + acc2[mt][nt][0] + brs) * 0.7071f;
            ho.y = (hc.y + acc2[mt][nt][1] + brs) * 0.7071f;
            *reinterpret_cast<float2*>(&hout[base + j0]) = ho;
            *reinterpret_cast<__half2*>(&hhout[base + j0]) = __floats2half2_rn(ho.x, ho.y);

            float2* sp = reinterpret_cast<float2*>(&g_skip[base + j0]);
            float2 sv;
            sv.x = acc2[mt][nt][2] + bsk;
            sv.y = acc2[mt][nt][3] + bsk;
            if (!first) {
                float2 old = *sp;
                sv.x += old.x; sv.y += old.y;
            }
            *sp = sv;
        }
    }
}

// ---------------- output head: relu -> 1x1 (64->64) -> relu -> 1x1 (64->1) ----------------
__global__ __launch_bounds__(256) void output_kernel(const float* __restrict__ ow1,
                                                     const float* __restrict__ ob1,
                                                     const float* __restrict__ ow2,
                                                     const float* __restrict__ ob2,
                                                     float* __restrict__ out) {
    __shared__ float sS[64 * 65];    // skip tile, [c][t]
    __shared__ float sW[64 * 68];    // ow1 transposed: [c][u]
    __shared__ float sw2[64], sb1[64];
    int tid = threadIdx.x;
    int n0 = blockIdx.x * 64;
    int b = n0 >> 14, t0 = n0 & 16383;

    for (int idx = tid; idx < 64 * 64; idx += 256) {
        int c = idx >> 6, tt = idx & 63;
        sS[c * 65 + tt] = g_skip[(b * 64 + c) * Tt + t0 + tt];
    }
    for (int idx = tid; idx < 64 * 64; idx += 256) {
        int u = idx >> 6, c = idx & 63;
        sW[c * 68 + u] = ow1[idx];             // ow1[u][c]
    }
    if (tid < 64) { sw2[tid] = ow2[tid]; sb1[tid] = ob1[tid]; }
    __syncthreads();

    int tl = tid >> 2, p = tid & 3;            // 64 timesteps x 4-thread quads
    float acc[16];
#pragma unroll
    for (int q = 0; q < 16; q++) acc[q] = sb1[4 * q + p];
#pragma unroll 4
    for (int c = 0; c < 64; c++) {
        float v = fmaxf(sS[c * 65 + tl], 0.f);
#pragma unroll
        for (int q = 0; q < 16; q++) acc[q] = fmaf(sW[c * 68 + 4 * q + p], v, acc[q]);
    }
    float y = 0.f;
#pragma unroll
    for (int q = 0; q < 16; q++) y += sw2[4 * q + p] * fmaxf(acc[q], 0.f);
    y += __shfl_xor_sync(0xFFFFFFFFu, y, 1);
    y += __shfl_xor_sync(0xFFFFFFFFu, y, 2);
    if (p == 0) out[b * Tt + t0 + tl] = y + ob2[0];
}

// ---------------- launcher ----------------
extern "C" void kernel_launch(void* const* d_in, const int* in_sizes, int n_in,
                              void* d_out, int out_size) {
    (void)in_sizes; (void)n_in; (void)out_size;
    const float* x    = (const float*)d_in[0];
    const float* w_in = (const float*)d_in[1];
    const float* b_in = (const float*)d_in[2];
    const float* fw   = (const float*)d_in[3];
    const float* fb   = (const float*)d_in[4];
    const float* gw   = (const float*)d_in[5];
    const float* gb   = (const float*)d_in[6];
    const float* rw   = (const float*)d_in[7];
    const float* rb   = (const float*)d_in[8];
    const float* sw   = (const float*)d_in[9];
    const float* sb   = (const float*)d_in[10];
    const float* ow1  = (const float*)d_in[11];
    const float* ob1  = (const float*)d_in[12];
    const float* ow2  = (const float*)d_in[13];
    const float* ob2  = (const float*)d_in[14];
    float* out = (float*)d_out;

    static const int dil[Ll] = {1, 2, 4, 8, 16, 32, 64, 128, 256, 512};

    cudaFuncSetAttribute((const void*)layer_kernel,
                         cudaFuncAttributeMaxDynamicSharedMemorySize, SMEM_BYTES);

    prep_kernel<<<960, 256>>>(fw, fb, gw, gb, rw, rb, sw, sb);
    input_conv_kernel<<<(Bb * Tt) / 128, 256>>>(x, w_in, b_in);

    int buf = 0;
    for (int l = 0; l < Ll; l++) {
        layer_kernel<<<(Bb * Tt) / NT, 256, SMEM_BYTES>>>(l, dil[l], buf, l == 0);
        buf ^= 1;
    }
    output_kernel<<<(Bb * Tt) / 64, 256>>>(ow1, ob1, ow2, ob2, out);
}

// round 7
// speedup vs baseline: 1.1878x; 1.1691x over previous
#include <cuda_runtime.h>
#include <cuda_fp16.h>
#include <cstdint>

#define Bb 16
#define Tt 16384
#define Ll 10
#define NTILE 512
#define CHUNK 128

// ---------------- scratch (static __device__, no allocs) ----------------
__device__ float  g_h[2][Bb * 64 * Tt];      // fp32 residual stream, double buffered
__device__ __half g_hh[2][Bb * 64 * Tt];     // fp16 shadow of h (GEMM operand)
__device__ __half g_act[Ll][Bb * 64 * Tt];   // per-layer gated activations (fp16)
__device__ __half g_W1[Ll * 128 * 192];      // interleaved (filt/gate) dilated-conv weights
__device__ __half g_W2[Ll * 64 * 64];        // res 1x1 weights (k-major)
__device__ __half g_Wsk[64 * 640];           // skip weights: [o][l*64+i]
__device__ float  g_b1[Ll * 128];            // interleaved fb/gb
__device__ float  g_rb[Ll * 64];
__device__ float  g_bsum[64];                // sum_l sb[l][o]

// ---------------- mma / ldmatrix / cp.async helpers ----------------
__device__ __forceinline__ void mma16816(float c[4], const uint32_t a[4], const uint32_t b[2]) {
    asm volatile(
        "mma.sync.aligned.m16n8k16.row.col.f32.f16.f16.f32 "
        "{%0,%1,%2,%3}, {%4,%5,%6,%7}, {%8,%9}, {%0,%1,%2,%3};\n"
        : "+f"(c[0]), "+f"(c[1]), "+f"(c[2]), "+f"(c[3])
        : "r"(a[0]), "r"(a[1]), "r"(a[2]), "r"(a[3]), "r"(b[0]), "r"(b[1]));
}
__device__ __forceinline__ void ldsm4(uint32_t r[4], uint32_t addr) {
    asm volatile("ldmatrix.sync.aligned.m8n8.x4.shared.b16 {%0,%1,%2,%3}, [%4];"
                 : "=r"(r[0]), "=r"(r[1]), "=r"(r[2]), "=r"(r[3]) : "r"(addr));
}
__device__ __forceinline__ void ldsm4t(uint32_t r[4], uint32_t addr) {
    asm volatile("ldmatrix.sync.aligned.m8n8.x4.trans.shared.b16 {%0,%1,%2,%3}, [%4];"
                 : "=r"(r[0]), "=r"(r[1]), "=r"(r[2]), "=r"(r[3]) : "r"(addr));
}
__device__ __forceinline__ void cpa4(uint32_t dst, const void* src, int sz) {
    asm volatile("cp.async.ca.shared.global [%0], [%1], 4, %2;" :: "r"(dst), "l"(src), "r"(sz));
}
__device__ __forceinline__ void cpa16(uint32_t dst, const void* src) {
    asm volatile("cp.async.ca.shared.global [%0], [%1], 16;" :: "r"(dst), "l"(src));
}
#define CP_COMMIT asm volatile("cp.async.commit_group;")
#define CP_WAIT0  asm volatile("cp.async.wait_group 0;")

// ---------------- weight prep ----------------
__global__ void prep_kernel(const float* __restrict__ fw, const float* __restrict__ fb,
                            const float* __restrict__ gw, const float* __restrict__ gb,
                            const float* __restrict__ rw, const float* __restrict__ rb,
                            const float* __restrict__ sw, const float* __restrict__ sb) {
    int idx = blockIdx.x * blockDim.x + threadIdx.x;
    if (idx < Ll * 128 * 192) {   // W1 interleaved filt/gate
        int l = idx / (128 * 192);
        int rem = idx - l * 128 * 192;
        int row = rem / 192, r = rem - row * 192;
        int k = r >> 6, i = r & 63;
        int tile = row >> 4, rr = row & 15;
        int o = tile * 8 + (rr & 7);
        int src = ((l * 64 + o) * 64 + i) * 3 + k;
        float v = (rr < 8) ? fw[src] : gw[src];
        g_W1[idx] = __float2half_rn(v);
    }
    if (idx < Ll * 64 * 64) {     // W2 = rw, k-major copy
        g_W2[idx] = __float2half_rn(rw[idx]);
    }
    if (idx < 64 * 640) {         // Wsk[o][l*64+i] = sw[l][o][i]
        int o = idx / 640, kk = idx - o * 640;
        int l = kk >> 6, i = kk & 63;
        g_Wsk[idx] = __float2half_rn(sw[(l * 64 + o) * 64 + i]);
    }
    if (idx < Ll * 128) {         // interleaved conv biases
        int l = idx >> 7, row = idx & 127;
        int tile = row >> 4, rr = row & 15;
        int o = tile * 8 + (rr & 7);
        g_b1[idx] = (rr < 8) ? fb[l * 64 + o] : gb[l * 64 + o];
    }
    if (idx < Ll * 64) g_rb[idx] = rb[idx];
    if (idx < 64) {
        float s = 0.f;
        for (int l = 0; l < Ll; l++) s += sb[l * 64 + idx];
        g_bsum[idx] = s;
    }
}

// ---------------- input 1x1 conv: x[B,T,F=32] -> h0[B,C=64,T] ----------------
__global__ __launch_bounds__(256) void input_conv_kernel(const float* __restrict__ x,
                                                         const float* __restrict__ w,
                                                         const float* __restrict__ bias) {
    __shared__ float sx[128 * 33];
    __shared__ float swt[64 * 32];
    __shared__ float sb[64];
    int tid = threadIdx.x;
    int n0 = blockIdx.x * 128;
    int b = n0 >> 14, t0 = n0 & 16383;

    for (int idx = tid; idx < 128 * 32; idx += 256) {
        int j = idx >> 5, f = idx & 31;
        sx[j * 33 + f] = x[(b * Tt + t0 + j) * 32 + f];
    }
    for (int idx = tid; idx < 2048; idx += 256) swt[idx] = w[idx];
    if (tid < 64) sb[tid] = bias[tid];
    __syncthreads();

    for (int oi = tid; oi < 64 * 128; oi += 256) {
        int c = oi >> 7, j = oi & 127;
        float s = sb[c];
#pragma unroll
        for (int f = 0; f < 32; f++) s = fmaf(swt[c * 32 + f], sx[j * 33 + f], s);
        int ofs = (b * 64 + c) * Tt + t0 + j;
        g_h[0][ofs] = s;
        g_hh[0][ofs] = __float2half_rn(s);
    }
}

// ---------------- per-layer fused kernel (NT=512, pipelined) ----------------
// smem halves: W1 [128][200] @0, W2 [64][72] @25600, sAct [64][136] @30208,
//              sX0 [192][136] @38912, sX1 @65024. Total 91136 halves = 182272 B.
#define ST_X   136
#define ST_W1  200
#define ST_W2  72
#define ST_ACT 136
#define OFF_W1h  0
#define OFF_W2h  25600
#define OFF_ACTh 30208
#define OFF_X0h  38912
#define OFF_X1h  65024
#define L_SMEM_BYTES (91136 * 2)

__device__ __forceinline__ void issue_gather(uint32_t su, int xoff_h,
                                             const __half* __restrict__ hhin,
                                             int b, int tc0, int d, int tid) {
#pragma unroll 6
    for (int it = 0; it < 24; it++) {
        int idx = tid + it * 512;          // 192*64 = 12288 half2 slots
        int r = idx >> 6, q = idx & 63;
        int j = q * 2;
        int k = r >> 6, i = r & 63;
        int off = (2 - k) * d;
        int t = tc0 + j - off;
        uint32_t dst = su + (uint32_t)(xoff_h + r * ST_X + j) * 2;
        const __half* src = hhin + ((b * 64 + i) * Tt + t);
        if (off & 1) {                      // odd offset (layer d=1 tap): scalar
            __half lo = (t >= 0) ? src[0] : __ushort_as_half(0);
            __half hi = (t + 1 >= 0) ? src[1] : __ushort_as_half(0);
            __half2 v = __halves2half2(lo, hi);
            asm volatile("st.shared.b32 [%0], %1;" :: "r"(dst), "r"(*reinterpret_cast<uint32_t*>(&v)));
        } else {
            cpa4(dst, src, (t >= 0) ? 4 : 0);
        }
    }
}

__global__ void __launch_bounds__(512, 1) layer_kernel(int l, int d, int bufin) {
    extern __shared__ __half smh[];
    const uint32_t su = (uint32_t)__cvta_generic_to_shared(smh);

    const int tid = threadIdx.x;
    const int lane = tid & 31, wid = tid >> 5;
    const int g = lane >> 2, tig = lane & 3;
    const int l15 = lane & 15;
    const int lc8 = (lane >> 4) << 3;
    // GEMM1 map: 4 m-groups x 4 n-groups
    const int wm1 = (wid >> 2) * 32, wn1 = (wid & 3) * 32;
    // GEMM2 map: 2 m-groups x 8 n-groups
    const int wm2 = (wid >> 3) * 32, wn2 = (wid & 7) * 16;

    const int n0 = blockIdx.x * NTILE;
    const int b = n0 >> 14;
    const int t0 = n0 & 16383;

    const float* __restrict__ hin = g_h[bufin];
    float* __restrict__ hout = g_h[bufin ^ 1];
    const __half* __restrict__ hhin = g_hh[bufin];
    __half* __restrict__ hhout = g_hh[bufin ^ 1];
    __half* __restrict__ actout = g_act[l];

    // ---- prologue: stage W1 (3072 x 16B), W2 (512 x 16B), gather chunk 0 ----
    {
        const __half* W1g = g_W1 + l * 128 * 192;
#pragma unroll
        for (int it = 0; it < 6; it++) {
            int idx = tid + it * 512;       // 3072 = 128 rows x 24 x 16B
            int r = idx / 24, c = idx - r * 24;
            cpa16(su + (uint32_t)(OFF_W1h + r * ST_W1 + c * 8) * 2, W1g + r * 192 + c * 8);
        }
        const __half* W2g = g_W2 + l * 64 * 64;
        {
            int r = tid >> 3, c = tid & 7;  // 512 = 64 rows x 8 x 16B
            cpa16(su + (uint32_t)(OFF_W2h + r * ST_W2 + c * 8) * 2, W2g + r * 64 + c * 8);
        }
    }
    issue_gather(su, OFF_X0h, hhin, b, t0, d, tid);
    CP_COMMIT;

    // per-thread biases
    float bfil[2], bgat[2], brs[2][2];
#pragma unroll
    for (int mt = 0; mt < 2; mt++) {
        int tile1 = (wid >> 2) * 2 + mt;
        bfil[mt] = g_b1[l * 128 + tile1 * 16 + g];
        bgat[mt] = g_b1[l * 128 + tile1 * 16 + 8 + g];
        int tile2 = (wid >> 3) * 2 + mt;
        brs[mt][0] = g_rb[l * 64 + tile2 * 16 + g];
        brs[mt][1] = g_rb[l * 64 + tile2 * 16 + 8 + g];
    }

    for (int c = 0; c < 4; c++) {
        const int tc = t0 + c * CHUNK;
        const int xcur = (c & 1) ? OFF_X1h : OFF_X0h;
        CP_WAIT0;
        __syncthreads();
        if (c < 3) {
            issue_gather(su, (c & 1) ? OFF_X0h : OFF_X1h, hhin, b, tc + CHUNK, d, tid);
            CP_COMMIT;
        }
        // prefetch hin (residual) for this chunk
        float2 hpre[2][2][2];
#pragma unroll
        for (int mt = 0; mt < 2; mt++) {
            int o_a = ((wid >> 3) * 2 + mt) * 16 + g;
#pragma unroll
            for (int nt = 0; nt < 2; nt++) {
                int j0 = wn2 + nt * 8 + 2 * tig;
                hpre[mt][nt][0] = *reinterpret_cast<const float2*>(&hin[(b * 64 + o_a) * Tt + tc + j0]);
                hpre[mt][nt][1] = *reinterpret_cast<const float2*>(&hin[(b * 64 + o_a + 8) * Tt + tc + j0]);
            }
        }

        // ---- GEMM1: [128 x 192] x [192 x 128] ----
        float acc[2][4][4];
#pragma unroll
        for (int mt = 0; mt < 2; mt++)
#pragma unroll
            for (int nt = 0; nt < 4; nt++)
#pragma unroll
                for (int q = 0; q < 4; q++) acc[mt][nt][q] = 0.f;
        {
            uint32_t aAddr = su + (uint32_t)(OFF_W1h + (wm1 + l15) * ST_W1 + lc8) * 2;
            uint32_t bAddr = su + (uint32_t)(xcur + l15 * ST_X + wn1 + lc8) * 2;
#pragma unroll
            for (int kb = 0; kb < 12; kb++) {
                uint32_t a0[4], a1[4];
                ldsm4(a0, aAddr);
                ldsm4(a1, aAddr + 16 * ST_W1 * 2);
                uint32_t bf0[4], bf1[4];
                ldsm4t(bf0, bAddr);
                ldsm4t(bf1, bAddr + 32);
                mma16816(acc[0][0], a0, &bf0[0]);
                mma16816(acc[0][1], a0, &bf0[2]);
                mma16816(acc[0][2], a0, &bf1[0]);
                mma16816(acc[0][3], a0, &bf1[2]);
                mma16816(acc[1][0], a1, &bf0[0]);
                mma16816(acc[1][1], a1, &bf0[2]);
                mma16816(acc[1][2], a1, &bf1[0]);
                mma16816(acc[1][3], a1, &bf1[2]);
                aAddr += 32;
                bAddr += 16 * ST_X * 2;
            }
        }
        // ---- epilogue1: act = tanh(filt)*sigmoid(gate) -> sAct + global act ----
#pragma unroll
        for (int mt = 0; mt < 2; mt++) {
            int o = ((wid >> 2) * 2 + mt) * 8 + g;
#pragma unroll
            for (int nt = 0; nt < 4; nt++) {
                int j0 = wn1 + nt * 8 + 2 * tig;
                float f0 = 1.f - 2.f / (__expf(2.f * (acc[mt][nt][0] + bfil[mt])) + 1.f);
                float f1 = 1.f - 2.f / (__expf(2.f * (acc[mt][nt][1] + bfil[mt])) + 1.f);
                float s0 = 1.f / (1.f + __expf(-(acc[mt][nt][2] + bgat[mt])));
                float s1 = 1.f / (1.f + __expf(-(acc[mt][nt][3] + bgat[mt])));
                __half2 av = __floats2half2_rn(f0 * s0, f1 * s1);
                *reinterpret_cast<__half2*>(smh + OFF_ACTh + o * ST_ACT + j0) = av;
                *reinterpret_cast<__half2*>(&actout[(b * 64 + o) * Tt + tc + j0]) = av;
            }
        }
        __syncthreads();

        // ---- GEMM2 (res only): [64 x 64] x [64 x 128] ----
        float acc2[2][2][4];
#pragma unroll
        for (int mt = 0; mt < 2; mt++)
#pragma unroll
            for (int nt = 0; nt < 2; nt++)
#pragma unroll
                for (int q = 0; q < 4; q++) acc2[mt][nt][q] = 0.f;
        {
            uint32_t aAddr = su + (uint32_t)(OFF_W2h + (wm2 + l15) * ST_W2 + lc8) * 2;
            uint32_t bAddr = su + (uint32_t)(OFF_ACTh + l15 * ST_ACT + wn2 + lc8) * 2;
#pragma unroll
            for (int kb = 0; kb < 4; kb++) {
                uint32_t a0[4], a1[4];
                ldsm4(a0, aAddr);
                ldsm4(a1, aAddr + 16 * ST_W2 * 2);
                uint32_t bf0[4];
                ldsm4t(bf0, bAddr);
                mma16816(acc2[0][0], a0, &bf0[0]);
                mma16816(acc2[0][1], a0, &bf0[2]);
                mma16816(acc2[1][0], a1, &bf0[0]);
                mma16816(acc2[1][1], a1, &bf0[2]);
                aAddr += 32;
                bAddr += 16 * ST_ACT * 2;
            }
        }
        // ---- epilogue2: h' = (h + res)*0.7071 ----
#pragma unroll
        for (int mt = 0; mt < 2; mt++) {
            int o_a = ((wid >> 3) * 2 + mt) * 16 + g;
#pragma unroll
            for (int nt = 0; nt < 2; nt++) {
                int j0 = wn2 + nt * 8 + 2 * tig;
                float2 ha = hpre[mt][nt][0];
                float2 hb = hpre[mt][nt][1];
                float2 ya, yb;
                ya.x = (ha.x + acc2[mt][nt][0] + brs[mt][0]) * 0.7071f;
                ya.y = (ha.y + acc2[mt][nt][1] + brs[mt][0]) * 0.7071f;
                yb.x = (hb.x + acc2[mt][nt][2] + brs[mt][1]) * 0.7071f;
                yb.y = (hb.y + acc2[mt][nt][3] + brs[mt][1]) * 0.7071f;
                int basea = (b * 64 + o_a) * Tt + tc + j0;
                int baseb = (b * 64 + o_a + 8) * Tt + tc + j0;
                *reinterpret_cast<float2*>(&hout[basea]) = ya;
                *reinterpret_cast<float2*>(&hout[baseb]) = yb;
                *reinterpret_cast<__half2*>(&hhout[basea]) = __floats2half2_rn(ya.x, ya.y);
                *reinterpret_cast<__half2*>(&hhout[baseb]) = __floats2half2_rn(yb.x, yb.y);
            }
        }
    }
}

// ---------------- fused output: skip GEMM (K=640) + relu + fp32 head ----------------
// smem halves: Wsk [64][648] @0, actbuf0 [64][136] @41472, actbuf1 @50176 (end 58880h = 117760B)
// fp32 @117760: sS [64][132], sW1o [64][68], sw2[64], sb1[64]  (total 169472B)
#define ST_WSK 648
#define OFFO_A0h 41472
#define OFFO_A1h 50176
#define OFFO_F32 117760
#define O_SMEM_BYTES 169472

__global__ void __launch_bounds__(512, 1) output_kernel(const float* __restrict__ ow1,
                                                        const float* __restrict__ ob1,
                                                        const float* __restrict__ ow2,
                                                        const float* __restrict__ ob2,
                                                        float* __restrict__ out) {
    extern __shared__ __half smh[];
    const uint32_t su = (uint32_t)__cvta_generic_to_shared(smh);
    float* sS   = reinterpret_cast<float*>(reinterpret_cast<char*>(smh) + OFFO_F32);
    float* sW1o = sS + 64 * 132;
    float* sw2  = sW1o + 64 * 68;
    float* sb1  = sw2 + 64;

    const int tid = threadIdx.x;
    const int lane = tid & 31, wid = tid >> 5;
    const int g = lane >> 2, tig = lane & 3;
    const int l15 = lane & 15;
    const int lc8 = (lane >> 4) << 3;
    const int wm = (wid & 3) * 16;       // 4 m16 tiles
    const int wn = (wid >> 2) * 32;      // 4 n-groups of 32

    const int n0 = blockIdx.x * 128;
    const int b = n0 >> 14, t0 = n0 & 16383;

    // stage Wsk (64 rows x 80 x 16B chunks)
#pragma unroll
    for (int it = 0; it < 10; it++) {
        int idx = tid + it * 512;
        int r = idx / 80, c = idx - r * 80;
        cpa16(su + (uint32_t)(r * ST_WSK + c * 8) * 2, g_Wsk + r * 640 + c * 8);
    }
    // stage act layer 0
    {
        const __half* a0 = g_act[0];
#pragma unroll
        for (int it = 0; it < 2; it++) {
            int idx = tid + it * 512;       // 64 rows x 16 x 16B
            int r = idx >> 4, c = idx & 15;
            cpa16(su + (uint32_t)(OFFO_A0h + r * ST_X + c * 8) * 2,
                  a0 + (b * 64 + r) * Tt + t0 + c * 8);
        }
    }
    CP_COMMIT;
    // stage fp32 head weights (plain)
    for (int idx = tid; idx < 4096; idx += 512) {
        int u = idx >> 6, cch = idx & 63;
        sW1o[cch * 68 + u] = ow1[idx];
    }
    if (tid < 64) { sw2[tid] = ow2[tid]; sb1[tid] = ob1[tid]; }

    float acc[4][4];
#pragma unroll
    for (int nt = 0; nt < 4; nt++)
#pragma unroll
        for (int q = 0; q < 4; q++) acc[nt][q] = 0.f;

    for (int l = 0; l < Ll; l++) {
        CP_WAIT0;
        __syncthreads();
        if (l < Ll - 1) {
            const __half* an = g_act[l + 1];
            int dsth = ((l + 1) & 1) ? OFFO_A1h : OFFO_A0h;
#pragma unroll
            for (int it = 0; it < 2; it++) {
                int idx = tid + it * 512;
                int r = idx >> 4, c = idx & 15;
                cpa16(su + (uint32_t)(dsth + r * ST_X + c * 8) * 2,
                      an + (b * 64 + r) * Tt + t0 + c * 8);
            }
            CP_COMMIT;
        }
        int abuf = (l & 1) ? OFFO_A1h : OFFO_A0h;
#pragma unroll
        for (int kb = 0; kb < 4; kb++) {
            uint32_t a0[4];
            ldsm4(a0, su + (uint32_t)((wm + l15) * ST_WSK + l * 64 + kb * 16 + lc8) * 2);
            uint32_t bf0[4], bf1[4];
            uint32_t bAddr = su + (uint32_t)(abuf + (kb * 16 + l15) * ST_X + wn + lc8) * 2;
            ldsm4t(bf0, bAddr);
            ldsm4t(bf1, bAddr + 32);
            mma16816(acc[0], a0, &bf0[0]);
            mma16816(acc[1], a0, &bf0[2]);
            mma16816(acc[2], a0, &bf1[0]);
            mma16816(acc[3], a0, &bf1[2]);
        }
    }
    // write relu(skip_sum + bsum) into sS
    {
        int o_a = wm + g, o_b = wm + 8 + g;
        float ba = g_bsum[o_a], bb = g_bsum[o_b];
#pragma unroll
        for (int nt = 0; nt < 4; nt++) {
            int j0 = wn + nt * 8 + 2 * tig;
            sS[o_a * 132 + j0]     = fmaxf(acc[nt][0] + ba, 0.f);
            sS[o_a * 132 + j0 + 1] = fmaxf(acc[nt][1] + ba, 0.f);
            sS[o_b * 132 + j0]     = fmaxf(acc[nt][2] + bb, 0.f);
            sS[o_b * 132 + j0 + 1] = fmaxf(acc[nt][3] + bb, 0.f);
        }
    }
    __syncthreads();

    // fp32 scalar head: relu(ow1 . s + ob1), then ow2 . u + ob2
    {
        int tl = tid >> 2, p = tid & 3;      // 128 timesteps x 4-thread quads
        float a2[16];
#pragma unroll
        for (int q = 0; q < 16; q++) a2[q] = sb1[4 * q + p];
#pragma unroll 4
        for (int cch = 0; cch < 64; cch++) {
            float v = sS[cch * 132 + tl];    // already relu'd
#pragma unroll
            for (int q = 0; q < 16; q++) a2[q] = fmaf(sW1o[cch * 68 + 4 * q + p], v, a2[q]);
        }
        float y = 0.f;
#pragma unroll
        for (int q = 0; q < 16; q++) y += sw2[4 * q + p] * fmaxf(a2[q], 0.f);
        y += __shfl_xor_sync(0xFFFFFFFFu, y, 1);
        y += __shfl_xor_sync(0xFFFFFFFFu, y, 2);
        if (p == 0) out[b * Tt + t0 + tl] = y + ob2[0];
    }
}

// ---------------- launcher ----------------
extern "C" void kernel_launch(void* const* d_in, const int* in_sizes, int n_in,
                              void* d_out, int out_size) {
    (void)in_sizes; (void)n_in; (void)out_size;
    const float* x    = (const float*)d_in[0];
    const float* w_in = (const float*)d_in[1];
    const float* b_in = (const float*)d_in[2];
    const float* fw   = (const float*)d_in[3];
    const float* fb   = (const float*)d_in[4];
    const float* gw   = (const float*)d_in[5];
    const float* gb   = (const float*)d_in[6];
    const float* rw   = (const float*)d_in[7];
    const float* rb   = (const float*)d_in[8];
    const float* sw   = (const float*)d_in[9];
    const float* sb   = (const float*)d_in[10];
    const float* ow1  = (const float*)d_in[11];
    const float* ob1  = (const float*)d_in[12];
    const float* ow2  = (const float*)d_in[13];
    const float* ob2  = (const float*)d_in[14];
    float* out = (float*)d_out;

    static const int dil[Ll] = {1, 2, 4, 8, 16, 32, 64, 128, 256, 512};

    cudaFuncSetAttribute((const void*)layer_kernel,
                         cudaFuncAttributeMaxDynamicSharedMemorySize, L_SMEM_BYTES);
    cudaFuncSetAttribute((const void*)output_kernel,
                         cudaFuncAttributeMaxDynamicSharedMemorySize, O_SMEM_BYTES);

    prep_kernel<<<960, 256>>>(fw, fb, gw, gb, rw, rb, sw, sb);
    input_conv_kernel<<<(Bb * Tt) / 128, 256>>>(x, w_in, b_in);

    int buf = 0;
    for (int l = 0; l < Ll; l++) {
        layer_kernel<<<(Bb * Tt) / NTILE, 512, L_SMEM_BYTES>>>(l, dil[l], buf);
        buf ^= 1;
    }
    output_kernel<<<(Bb * Tt) / 128, 512, O_SMEM_BYTES>>>(ow1, ob1, ow2, ob2, out);
}

// round 10
// speedup vs baseline: 1.9208x; 1.6172x over previous
#include <cuda_runtime.h>
#include <cuda_fp16.h>
#include <cstdint>

#define Bb 16
#define Tt 16384
#define Ll 10
#define NTILE 512
#define CHUNK 128

// ---------------- scratch (static __device__, no allocs) ----------------
__device__ float  g_h[2][Bb * 64 * Tt];      // fp32 residual stream, double buffered
__device__ __half g_hh[2][Bb * 64 * Tt];     // fp16 shadow of h (GEMM operand)
__device__ __half g_act[Ll][Bb * 64 * Tt];   // per-layer gated activations (fp16)
__device__ __half g_W1[Ll * 128 * 192];      // interleaved (filt/gate) dilated-conv weights
__device__ __half g_W2[Ll * 64 * 64];        // res 1x1 weights (k-major)
__device__ __half g_Wsk[64 * 640];           // skip weights: [o][l*64+i]
__device__ float  g_b1[Ll * 128];            // interleaved fb/gb
__device__ float  g_rb[Ll * 64];
__device__ float  g_bsum[64];                // sum_l sb[l][o]

// ---------------- mma / ldmatrix / cp.async helpers ----------------
__device__ __forceinline__ void mma16816(float c[4], const uint32_t a[4], const uint32_t b[2]) {
    asm volatile(
        "mma.sync.aligned.m16n8k16.row.col.f32.f16.f16.f32 "
        "{%0,%1,%2,%3}, {%4,%5,%6,%7}, {%8,%9}, {%0,%1,%2,%3};\n"
        : "+f"(c[0]), "+f"(c[1]), "+f"(c[2]), "+f"(c[3])
        : "r"(a[0]), "r"(a[1]), "r"(a[2]), "r"(a[3]), "r"(b[0]), "r"(b[1]));
}
__device__ __forceinline__ void ldsm4(uint32_t r[4], uint32_t addr) {
    asm volatile("ldmatrix.sync.aligned.m8n8.x4.shared.b16 {%0,%1,%2,%3}, [%4];"
                 : "=r"(r[0]), "=r"(r[1]), "=r"(r[2]), "=r"(r[3]) : "r"(addr));
}
__device__ __forceinline__ void ldsm4t(uint32_t r[4], uint32_t addr) {
    asm volatile("ldmatrix.sync.aligned.m8n8.x4.trans.shared.b16 {%0,%1,%2,%3}, [%4];"
                 : "=r"(r[0]), "=r"(r[1]), "=r"(r[2]), "=r"(r[3]) : "r"(addr));
}
__device__ __forceinline__ void cpa4(uint32_t dst, const void* src, int sz) {
    asm volatile("cp.async.ca.shared.global [%0], [%1], 4, %2;" :: "r"(dst), "l"(src), "r"(sz));
}
__device__ __forceinline__ void cpa16(uint32_t dst, const void* src) {
    asm volatile("cp.async.ca.shared.global [%0], [%1], 16;" :: "r"(dst), "l"(src));
}
#define CP_COMMIT asm volatile("cp.async.commit_group;")
#define CP_WAIT0  asm volatile("cp.async.wait_group 0;")

// ---------------- weight prep ----------------
__global__ void prep_kernel(const float* __restrict__ fw, const float* __restrict__ fb,
                            const float* __restrict__ gw, const float* __restrict__ gb,
                            const float* __restrict__ rw, const float* __restrict__ rb,
                            const float* __restrict__ sw, const float* __restrict__ sb) {
    int idx = blockIdx.x * blockDim.x + threadIdx.x;
    if (idx < Ll * 128 * 192) {   // W1 interleaved filt/gate
        int l = idx / (128 * 192);
        int rem = idx - l * 128 * 192;
        int row = rem / 192, r = rem - row * 192;
        int k = r >> 6, i = r & 63;
        int tile = row >> 4, rr = row & 15;
        int o = tile * 8 + (rr & 7);
        int src = ((l * 64 + o) * 64 + i) * 3 + k;
        float v = (rr < 8) ? fw[src] : gw[src];
        g_W1[idx] = __float2half_rn(v);
    }
    if (idx < Ll * 64 * 64) {     // W2 = rw, k-major copy
        g_W2[idx] = __float2half_rn(rw[idx]);
    }
    if (idx < 64 * 640) {         // Wsk[o][l*64+i] = sw[l][o][i]
        int o = idx / 640, kk = idx - o * 640;
        int l = kk >> 6, i = kk & 63;
        g_Wsk[idx] = __float2half_rn(sw[(l * 64 + o) * 64 + i]);
    }
    if (idx < Ll * 128) {         // interleaved conv biases
        int l = idx >> 7, row = idx & 127;
        int tile = row >> 4, rr = row & 15;
        int o = tile * 8 + (rr & 7);
        g_b1[idx] = (rr < 8) ? fb[l * 64 + o] : gb[l * 64 + o];
    }
    if (idx < Ll * 64) g_rb[idx] = rb[idx];
    if (idx < 64) {
        float s = 0.f;
        for (int l = 0; l < Ll; l++) s += sb[l * 64 + idx];
        g_bsum[idx] = s;
    }
}

// ---------------- input 1x1 conv: x[B,T,F=32] -> h0[B,C=64,T] ----------------
__global__ __launch_bounds__(256) void input_conv_kernel(const float* __restrict__ x,
                                                         const float* __restrict__ w,
                                                         const float* __restrict__ bias) {
    __shared__ float sx[128 * 33];
    __shared__ float swt[64 * 32];
    __shared__ float sb[64];
    int tid = threadIdx.x;
    int n0 = blockIdx.x * 128;
    int b = n0 >> 14, t0 = n0 & 16383;

    for (int idx = tid; idx < 128 * 32; idx += 256) {
        int j = idx >> 5, f = idx & 31;
        sx[j * 33 + f] = x[(b * Tt + t0 + j) * 32 + f];
    }
    for (int idx = tid; idx < 2048; idx += 256) swt[idx] = w[idx];
    if (tid < 64) sb[tid] = bias[tid];
    __syncthreads();

    for (int oi = tid; oi < 64 * 128; oi += 256) {
        int c = oi >> 7, j = oi & 127;
        float s = sb[c];
#pragma unroll
        for (int f = 0; f < 32; f++) s = fmaf(swt[c * 32 + f], sx[j * 33 + f], s);
        int ofs = (b * 64 + c) * Tt + t0 + j;
        g_h[0][ofs] = s;
        g_hh[0][ofs] = __float2half_rn(s);
    }
}

// ---------------- per-layer fused kernel (NT=512, pipelined) ----------------
// smem halves: W1 [128][200] @0, W2 [64][72] @25600, sAct [64][136] @30208,
//              sX0 [192][136] @38912, sX1 @65024. Total 91136 halves = 182272 B.
#define ST_X   136
#define ST_W1  200
#define ST_W2  72
#define ST_ACT 136
#define OFF_W1h  0
#define OFF_W2h  25600
#define OFF_ACTh 30208
#define OFF_X0h  38912
#define OFF_X1h  65024
#define L_SMEM_BYTES (91136 * 2)

// narrow path (d=1,2): 4-byte ops, handles odd offsets via scalar smem store
__device__ __forceinline__ void issue_gather(uint32_t su, int xoff_h,
                                             const __half* __restrict__ hhin,
                                             int b, int tc0, int d, int tid) {
#pragma unroll 6
    for (int it = 0; it < 24; it++) {
        int idx = tid + it * 512;          // 192*64 = 12288 half2 slots
        int r = idx >> 6, q = idx & 63;
        int j = q * 2;
        int k = r >> 6, i = r & 63;
        int off = (2 - k) * d;
        int t = tc0 + j - off;
        uint32_t dst = su + (uint32_t)(xoff_h + r * ST_X + j) * 2;
        const __half* src = hhin + ((b * 64 + i) * Tt + t);
        if (off & 1) {                      // odd offset (d=1 tap): scalar
            __half lo = (t >= 0) ? src[0] : __ushort_as_half(0);
            __half hi = (t + 1 >= 0) ? src[1] : __ushort_as_half(0);
            __half2 v = __halves2half2(lo, hi);
            asm volatile("st.shared.b32 [%0], %1;" :: "r"(dst), "r"(*reinterpret_cast<uint32_t*>(&v)));
        } else {
            cpa4(dst, src, (t >= 0) ? 4 : 0);
        }
    }
}

// wide path: G = 16 (all offsets mult of 8: d>=8) or G = 8 (d=4).
// tb stays G/2-aligned so out-of-range chunks are fully negative -> zfill.
template <int G>
__device__ __forceinline__ void issue_gather_w(uint32_t su, int xoff_h,
                                               const __half* __restrict__ hhin,
                                               int b, int tc0, int d, int tid) {
    constexpr int PER = 256 / G;           // ops per 256B row
    constexpr int ITS = 192 * PER / 512;
#pragma unroll
    for (int it = 0; it < ITS; it++) {
        int idx = tid + it * 512;
        int r = idx / PER, cc = idx % PER;
        int k = r >> 6, i = r & 63;
        int off = (2 - k) * d;
        int tb = tc0 + cc * (G / 2) - off;
        uint32_t dst = su + (uint32_t)(xoff_h + r * ST_X + cc * (G / 2)) * 2;
        const __half* src = hhin + ((b * 64 + i) * Tt + (tb >= 0 ? tb : 0));
        int sz = (tb >= 0) ? G : 0;
        if (G == 16)
            asm volatile("cp.async.ca.shared.global [%0], [%1], 16, %2;" :: "r"(dst), "l"(src), "r"(sz));
        else
            asm volatile("cp.async.ca.shared.global [%0], [%1], 8, %2;" :: "r"(dst), "l"(src), "r"(sz));
    }
}

__device__ __forceinline__ void gather_dispatch(uint32_t su, int xoff_h,
                                                const __half* __restrict__ hhin,
                                                int b, int tc0, int d, int tid) {
    if (d >= 8)      issue_gather_w<16>(su, xoff_h, hhin, b, tc0, d, tid);
    else if (d == 4) issue_gather_w<8>(su, xoff_h, hhin, b, tc0, d, tid);
    else             issue_gather(su, xoff_h, hhin, b, tc0, d, tid);
}

__global__ void __launch_bounds__(512, 1) layer_kernel(int l, int d, int bufin) {
    extern __shared__ __half smh[];
    const uint32_t su = (uint32_t)__cvta_generic_to_shared(smh);

    const int tid = threadIdx.x;
    const int lane = tid & 31, wid = tid >> 5;
    const int g = lane >> 2, tig = lane & 3;
    const int l15 = lane & 15;
    const int lc8 = (lane >> 4) << 3;
    // GEMM1 map: 4 m-groups x 4 n-groups
    const int wm1 = (wid >> 2) * 32, wn1 = (wid & 3) * 32;
    // GEMM2 map: 2 m-groups x 8 n-groups
    const int wm2 = (wid >> 3) * 32, wn2 = (wid & 7) * 16;

    const int n0 = blockIdx.x * NTILE;
    const int b = n0 >> 14;
    const int t0 = n0 & 16383;

    const float* __restrict__ hin = g_h[bufin];
    float* __restrict__ hout = g_h[bufin ^ 1];
    const __half* __restrict__ hhin = g_hh[bufin];
    __half* __restrict__ hhout = g_hh[bufin ^ 1];
    __half* __restrict__ actout = g_act[l];

    // ---- prologue: stage W1 (3072 x 16B), W2 (512 x 16B), gather chunk 0 ----
    {
        const __half* W1g = g_W1 + l * 128 * 192;
#pragma unroll
        for (int it = 0; it < 6; it++) {
            int idx = tid + it * 512;       // 3072 = 128 rows x 24 x 16B
            int r = idx / 24, c = idx - r * 24;
            cpa16(su + (uint32_t)(OFF_W1h + r * ST_W1 + c * 8) * 2, W1g + r * 192 + c * 8);
        }
        const __half* W2g = g_W2 + l * 64 * 64;
        {
            int r = tid >> 3, c = tid & 7;  // 512 = 64 rows x 8 x 16B
            cpa16(su + (uint32_t)(OFF_W2h + r * ST_W2 + c * 8) * 2, W2g + r * 64 + c * 8);
        }
    }
    gather_dispatch(su, OFF_X0h, hhin, b, t0, d, tid);
    CP_COMMIT;

    // per-thread biases
    float bfil[2], bgat[2], brs[2][2];
#pragma unroll
    for (int mt = 0; mt < 2; mt++) {
        int tile1 = (wid >> 2) * 2 + mt;
        bfil[mt] = g_b1[l * 128 + tile1 * 16 + g];
        bgat[mt] = g_b1[l * 128 + tile1 * 16 + 8 + g];
        int tile2 = (wid >> 3) * 2 + mt;
        brs[mt][0] = g_rb[l * 64 + tile2 * 16 + g];
        brs[mt][1] = g_rb[l * 64 + tile2 * 16 + 8 + g];
    }

    for (int c = 0; c < 4; c++) {
        const int tc = t0 + c * CHUNK;
        const int xcur = (c & 1) ? OFF_X1h : OFF_X0h;
        CP_WAIT0;
        __syncthreads();
        if (c < 3) {
            gather_dispatch(su, (c & 1) ? OFF_X0h : OFF_X1h, hhin, b, tc + CHUNK, d, tid);
            CP_COMMIT;
        }
        // prefetch hin (residual) for this chunk
        float2 hpre[2][2][2];
#pragma unroll
        for (int mt = 0; mt < 2; mt++) {
            int o_a = ((wid >> 3) * 2 + mt) * 16 + g;
#pragma unroll
            for (int nt = 0; nt < 2; nt++) {
                int j0 = wn2 + nt * 8 + 2 * tig;
                hpre[mt][nt][0] = *reinterpret_cast<const float2*>(&hin[(b * 64 + o_a) * Tt + tc + j0]);
                hpre[mt][nt][1] = *reinterpret_cast<const float2*>(&hin[(b * 64 + o_a + 8) * Tt + tc + j0]);
            }
        }

        // ---- GEMM1: [128 x 192] x [192 x 128] ----
        float acc[2][4][4];
#pragma unroll
        for (int mt = 0; mt < 2; mt++)
#pragma unroll
            for (int nt = 0; nt < 4; nt++)
#pragma unroll
                for (int q = 0; q < 4; q++) acc[mt][nt][q] = 0.f;
        {
            uint32_t aAddr = su + (uint32_t)(OFF_W1h + (wm1 + l15) * ST_W1 + lc8) * 2;
            uint32_t bAddr = su + (uint32_t)(xcur + l15 * ST_X + wn1 + lc8) * 2;
#pragma unroll
            for (int kb = 0; kb < 12; kb++) {
                uint32_t a0[4], a1[4];
                ldsm4(a0, aAddr);
                ldsm4(a1, aAddr + 16 * ST_W1 * 2);
                uint32_t bf0[4], bf1[4];
                ldsm4t(bf0, bAddr);
                ldsm4t(bf1, bAddr + 32);
                mma16816(acc[0][0], a0, &bf0[0]);
                mma16816(acc[0][1], a0, &bf0[2]);
                mma16816(acc[0][2], a0, &bf1[0]);
                mma16816(acc[0][3], a0, &bf1[2]);
                mma16816(acc[1][0], a1, &bf0[0]);
                mma16816(acc[1][1], a1, &bf0[2]);
                mma16816(acc[1][2], a1, &bf1[0]);
                mma16816(acc[1][3], a1, &bf1[2]);
                aAddr += 32;
                bAddr += 16 * ST_X * 2;
            }
        }
        // ---- epilogue1: act = tanh(filt)*sigmoid(gate) -> sAct + global act ----
#pragma unroll
        for (int mt = 0; mt < 2; mt++) {
            int o = ((wid >> 2) * 2 + mt) * 8 + g;
#pragma unroll
            for (int nt = 0; nt < 4; nt++) {
                int j0 = wn1 + nt * 8 + 2 * tig;
                float f0 = 1.f - 2.f / (__expf(2.f * (acc[mt][nt][0] + bfil[mt])) + 1.f);
                float f1 = 1.f - 2.f / (__expf(2.f * (acc[mt][nt][1] + bfil[mt])) + 1.f);
                float s0 = 1.f / (1.f + __expf(-(acc[mt][nt][2] + bgat[mt])));
                float s1 = 1.f / (1.f + __expf(-(acc[mt][nt][3] + bgat[mt])));
                __half2 av = __floats2half2_rn(f0 * s0, f1 * s1);
                *reinterpret_cast<__half2*>(smh + OFF_ACTh + o * ST_ACT + j0) = av;
                *reinterpret_cast<__half2*>(&actout[(b * 64 + o) * Tt + tc + j0]) = av;
            }
        }
        __syncthreads();

        // ---- GEMM2 (res only): [64 x 64] x [64 x 128] ----
        float acc2[2][2][4];
#pragma unroll
        for (int mt = 0; mt < 2; mt++)
#pragma unroll
            for (int nt = 0; nt < 2; nt++)
#pragma unroll
                for (int q = 0; q < 4; q++) acc2[mt][nt][q] = 0.f;
        {
            uint32_t aAddr = su + (uint32_t)(OFF_W2h + (wm2 + l15) * ST_W2 + lc8) * 2;
            uint32_t bAddr = su + (uint32_t)(OFF_ACTh + l15 * ST_ACT + wn2 + lc8) * 2;
#pragma unroll
            for (int kb = 0; kb < 4; kb++) {
                uint32_t a0[4], a1[4];
                ldsm4(a0, aAddr);
                ldsm4(a1, aAddr + 16 * ST_W2 * 2);
                uint32_t bf0[4];
                ldsm4t(bf0, bAddr);
                mma16816(acc2[0][0], a0, &bf0[0]);
                mma16816(acc2[0][1], a0, &bf0[2]);
                mma16816(acc2[1][0], a1, &bf0[0]);
                mma16816(acc2[1][1], a1, &bf0[2]);
                aAddr += 32;
                bAddr += 16 * ST_ACT * 2;
            }
        }
        // ---- epilogue2: h' = (h + res)*0.7071 ----
#pragma unroll
        for (int mt = 0; mt < 2; mt++) {
            int o_a = ((wid >> 3) * 2 + mt) * 16 + g;
#pragma unroll
            for (int nt = 0; nt < 2; nt++) {
                int j0 = wn2 + nt * 8 + 2 * tig;
                float2 ha = hpre[mt][nt][0];
                float2 hb = hpre[mt][nt][1];
                float2 ya, yb;
                ya.x = (ha.x + acc2[mt][nt][0] + brs[mt][0]) * 0.7071f;
                ya.y = (ha.y + acc2[mt][nt][1] + brs[mt][0]) * 0.7071f;
                yb.x = (hb.x + acc2[mt][nt][2] + brs[mt][1]) * 0.7071f;
                yb.y = (hb.y + acc2[mt][nt][3] + brs[mt][1]) * 0.7071f;
                int basea = (b * 64 + o_a) * Tt + tc + j0;
                int baseb = (b * 64 + o_a + 8) * Tt + tc + j0;
                *reinterpret_cast<float2*>(&hout[basea]) = ya;
                *reinterpret_cast<float2*>(&hout[baseb]) = yb;
                *reinterpret_cast<__half2*>(&hhout[basea]) = __floats2half2_rn(ya.x, ya.y);
                *reinterpret_cast<__half2*>(&hhout[baseb]) = __floats2half2_rn(yb.x, yb.y);
            }
        }
    }
}

// ---------------- fused output: skip GEMM (K=640) + relu + fp32 head ----------------
// Processes 512 timesteps per CTA in 4 chunks of 128 (Wsk staged once per CTA).
// smem halves: Wsk [64][648] @0, actbuf0 [64][136] @41472, actbuf1 @50176 (end 117760B)
// fp32 @117760: sS [64][132], sW1o [64][68], sw2[64], sb1[64]  (total 169472B)
#define ST_WSK 648
#define OFFO_A0h 41472
#define OFFO_A1h 50176
#define OFFO_F32 117760
#define O_SMEM_BYTES 169472

__device__ __forceinline__ void stage_act(uint32_t su, int dsth, const __half* __restrict__ a,
                                          int b, int tbase, int tid) {
#pragma unroll
    for (int it = 0; it < 2; it++) {
        int idx = tid + it * 512;           // 1024 = 64 rows x 16 x 16B
        int r = idx >> 4, c = idx & 15;
        cpa16(su + (uint32_t)(dsth + r * ST_X + c * 8) * 2,
              a + (b * 64 + r) * Tt + tbase + c * 8);
    }
}

__global__ void __launch_bounds__(512, 1) output_kernel(const float* __restrict__ ow1,
                                                        const float* __restrict__ ob1,
                                                        const float* __restrict__ ow2,
                                                        const float* __restrict__ ob2,
                                                        float* __restrict__ out) {
    extern __shared__ __half smh[];
    const uint32_t su = (uint32_t)__cvta_generic_to_shared(smh);
    float* sS   = reinterpret_cast<float*>(reinterpret_cast<char*>(smh) + OFFO_F32);
    float* sW1o = sS + 64 * 132;
    float* sw2  = sW1o + 64 * 68;
    float* sb1  = sw2 + 64;

    const int tid = threadIdx.x;
    const int lane = tid & 31, wid = tid >> 5;
    const int g = lane >> 2, tig = lane & 3;
    const int l15 = lane & 15;
    const int lc8 = (lane >> 4) << 3;
    const int wm = (wid & 3) * 16;       // 4 m16 tiles
    const int wn = (wid >> 2) * 32;      // 4 n-groups of 32

    const int n0 = blockIdx.x * 512;
    const int b = n0 >> 14, t0 = n0 & 16383;

    // stage Wsk (64 rows x 80 x 16B chunks) + act (l=0, chunk=0)
#pragma unroll
    for (int it = 0; it < 10; it++) {
        int idx = tid + it * 512;
        int r = idx / 80, c = idx - r * 80;
        cpa16(su + (uint32_t)(r * ST_WSK + c * 8) * 2, g_Wsk + r * 640 + c * 8);
    }
    stage_act(su, OFFO_A0h, g_act[0], b, t0, tid);
    CP_COMMIT;

    // stage fp32 head weights (plain)
    for (int idx = tid; idx < 4096; idx += 512) {
        int u = idx >> 6, cch = idx & 63;
        sW1o[cch * 68 + u] = ow1[idx];
    }
    if (tid < 64) { sw2[tid] = ow2[tid]; sb1[tid] = ob1[tid]; }

    for (int c = 0; c < 4; c++) {
        float acc[4][4];
#pragma unroll
        for (int nt = 0; nt < 4; nt++)
#pragma unroll
            for (int q = 0; q < 4; q++) acc[nt][q] = 0.f;

        for (int l = 0; l < Ll; l++) {
            int n = c * Ll + l;
            CP_WAIT0;
            __syncthreads();
            if (n < 4 * Ll - 1) {
                int nn = n + 1, nl = nn % Ll, ncc = nn / Ll;
                stage_act(su, (nn & 1) ? OFFO_A1h : OFFO_A0h, g_act[nl],
                          b, t0 + ncc * 128, tid);
                CP_COMMIT;
            }
            int abuf = (n & 1) ? OFFO_A1h : OFFO_A0h;
#pragma unroll
            for (int kb = 0; kb < 4; kb++) {
                uint32_t a0[4];
                ldsm4(a0, su + (uint32_t)((wm + l15) * ST_WSK + l * 64 + kb * 16 + lc8) * 2);
                uint32_t bf0[4], bf1[4];
                uint32_t bAddr = su + (uint32_t)(abuf + (kb * 16 + l15) * ST_X + wn + lc8) * 2;
                ldsm4t(bf0, bAddr);
                ldsm4t(bf1, bAddr + 32);
                mma16816(acc[0], a0, &bf0[0]);
                mma16816(acc[1], a0, &bf0[2]);
                mma16816(acc[2], a0, &bf1[0]);
                mma16816(acc[3], a0, &bf1[2]);
            }
        }
        // write relu(skip_sum + bsum) into sS
        {
            int o_a = wm + g, o_b = wm + 8 + g;
            float ba = g_bsum[o_a], bb = g_bsum[o_b];
#pragma unroll
            for (int nt = 0; nt < 4; nt++) {
                int j0 = wn + nt * 8 + 2 * tig;
                sS[o_a * 132 + j0]     = fmaxf(acc[nt][0] + ba, 0.f);
                sS[o_a * 132 + j0 + 1] = fmaxf(acc[nt][1] + ba, 0.f);
                sS[o_b * 132 + j0]     = fmaxf(acc[nt][2] + bb, 0.f);
                sS[o_b * 132 + j0 + 1] = fmaxf(acc[nt][3] + bb, 0.f);
            }
        }
        __syncthreads();

        // fp32 scalar head: relu(ow1 . s + ob1), then ow2 . u + ob2
        {
            int tl = tid >> 2, p = tid & 3;      // 128 timesteps x 4-thread quads
            float a2[16];
#pragma unroll
            for (int q = 0; q < 16; q++) a2[q] = sb1[4 * q + p];
#pragma unroll 4
            for (int cch = 0; cch < 64; cch++) {
                float v = sS[cch * 132 + tl];    // already relu'd
#pragma unroll
                for (int q = 0; q < 16; q++) a2[q] = fmaf(sW1o[cch * 68 + 4 * q + p], v, a2[q]);
            }
            float y = 0.f;
#pragma unroll
            for (int q = 0; q < 16; q++) y += sw2[4 * q + p] * fmaxf(a2[q], 0.f);
            y += __shfl_xor_sync(0xFFFFFFFFu, y, 1);
            y += __shfl_xor_sync(0xFFFFFFFFu, y, 2);
            if (p == 0) out[b * Tt + t0 + c * 128 + tl] = y + ob2[0];
        }
        __syncthreads();
    }
}

// ---------------- launcher ----------------
extern "C" void kernel_launch(void* const* d_in, const int* in_sizes, int n_in,
                              void* d_out, int out_size) {
    (void)in_sizes; (void)n_in; (void)out_size;
    const float* x    = (const float*)d_in[0];
    const float* w_in = (const float*)d_in[1];
    const float* b_in = (const float*)d_in[2];
    const float* fw   = (const float*)d_in[3];
    const float* fb   = (const float*)d_in[4];
    const float* gw   = (const float*)d_in[5];
    const float* gb   = (const float*)d_in[6];
    const float* rw   = (const float*)d_in[7];
    const float* rb   = (const float*)d_in[8];
    const float* sw   = (const float*)d_in[9];
    const float* sb   = (const float*)d_in[10];
    const float* ow1  = (const float*)d_in[11];
    const float* ob1  = (const float*)d_in[12];
    const float* ow2  = (const float*)d_in[13];
    const float* ob2  = (const float*)d_in[14];
    float* out = (float*)d_out;

    static const int dil[Ll] = {1, 2, 4, 8, 16, 32, 64, 128, 256, 512};

    cudaFuncSetAttribute((const void*)layer_kernel,
                         cudaFuncAttributeMaxDynamicSharedMemorySize, L_SMEM_BYTES);
    cudaFuncSetAttribute((const void*)output_kernel,
                         cudaFuncAttributeMaxDynamicSharedMemorySize, O_SMEM_BYTES);

    prep_kernel<<<960, 256>>>(fw, fb, gw, gb, rw, rb, sw, sb);
    input_conv_kernel<<<(Bb * Tt) / 128, 256>>>(x, w_in, b_in);

    int buf = 0;
    for (int l = 0; l < Ll; l++) {
        layer_kernel<<<(Bb * Tt) / NTILE, 512, L_SMEM_BYTES>>>(l, dil[l], buf);
        buf ^= 1;
    }
    output_kernel<<<(Bb * Tt) / 512, 512, O_SMEM_BYTES>>>(ow1, ob1, ow2, ob2, out);
}